// round 3
// baseline (speedup 1.0000x reference)
#include <cuda_runtime.h>
#include <cuda_fp16.h>
#include <math.h>

#define NN 8192
#define NB 32
#define NG 256
#define NE 65536
#define DK 512
#define HH 32
#define VB 2048
#define VF 512
#define EPS 1e-5f

// ---------------- device scratch ----------------
__device__ float g_c[NN], g_d[NN];
__device__ float g_sB[NN], g_sF[NN];
__device__ __half2 g_vnB[NN * VB / 2];   // normalized visual_body fp16 (32 MB)
__device__ __half2 g_vnF[NN * VF / 2];   // normalized visual_face fp16 (8 MB)
__device__ float g_P0[DK], g_P1[DK];
__device__ float g_M1[DK], g_M2[DK], g_M3[DK];
__device__ float g_cst[12];
// counting-sort scratch (edges grouped by dst)
__device__ int g_cntB[NN], g_cntF[NN];
__device__ int g_ptrB[NN], g_ptrF[NN];
__device__ int g_curB[NN], g_curF[NN];
__device__ int g_srcB[NE], g_srcF[NE];

// ---------------- helpers ----------------
__device__ __forceinline__ float blockReduceSum(float v, float* red) {
    int t = threadIdx.x;
    red[t] = v;
    __syncthreads();
    for (int s = blockDim.x >> 1; s > 0; s >>= 1) {
        if (t < s) red[t] += red[t + s];
        __syncthreads();
    }
    float r = red[0];
    __syncthreads();
    return r;
}

__device__ __forceinline__ float warpSum(float v) {
    #pragma unroll
    for (int o = 16; o; o >>= 1) v += __shfl_xor_sync(0xFFFFFFFFu, v, o);
    return v;
}

// ---------------- K0: precompute constants ----------------
__global__ void precompute_kernel(
    const float* __restrict__ Wq, const float* __restrict__ Wk, const float* __restrict__ Wv,
    const float* __restrict__ mlp_W, const float* __restrict__ mlp_b,
    const float* __restrict__ np_W, const float* __restrict__ np_b,
    const float* __restrict__ body_W, const float* __restrict__ body_b,
    const float* __restrict__ face_W, const float* __restrict__ face_b,
    const float* __restrict__ pb_W, const float* __restrict__ pb_b,
    const float* __restrict__ pf_W, const float* __restrict__ pf_b)
{
    __shared__ float red[512];
    __shared__ float sh_u2[HH], sh_u3[HH];
    __shared__ float sh_res[12];
    int t = threadIdx.x;   // 512 threads

    if (t < HH) {
        float a2 = 0.f, a3 = 0.f;
        #pragma unroll
        for (int j = 0; j < HH; ++j) {
            a2 += body_W[t * HH + j] * pb_W[j];
            a3 += face_W[t * HH + j] * pf_W[j];
        }
        sh_u2[t] = a2;
        sh_u3[t] = a3;
    }
    __syncthreads();

    float wq0 = Wq[t], wq1 = Wq[DK + t];
    float wk0 = Wk[t], wk1 = Wk[DK + t];
    float wv0 = Wv[t], wv1 = Wv[DK + t];

    float g00 = blockReduceSum(wq0 * wk0, red);
    float g01 = blockReduceSum(wq0 * wk1, red);
    float g10 = blockReduceSum(wq1 * wk0, red);
    float g11 = blockReduceSum(wq1 * wk1, red);
    float sum0 = blockReduceSum(wv0, red);
    float sum1 = blockReduceSum(wv1, red);
    float sq00 = blockReduceSum(wv0 * wv0, red);
    float sq01 = blockReduceSum(wv0 * wv1, red);
    float sq11 = blockReduceSum(wv1 * wv1, red);
    float bu1 = blockReduceSum(t < HH ? mlp_b[t] * np_W[t] : 0.f, red);
    float bu2 = blockReduceSum(t < HH ? mlp_b[t] * sh_u2[t] : 0.f, red);
    float bu3 = blockReduceSum(t < HH ? mlp_b[t] * sh_u3[t] : 0.f, red);
    float bvB = blockReduceSum(t < HH ? body_b[t] * pb_W[t] : 0.f, red);
    float bvF = blockReduceSum(t < HH ? face_b[t] * pf_W[t] : 0.f, red);

    if (t == 0) {
        float m0 = sum0 / (float)DK, m1 = sum1 / (float)DK;
        sh_res[0] = g00; sh_res[1] = g01; sh_res[2] = g10; sh_res[3] = g11;
        sh_res[4] = sq00 / (float)DK - m0 * m0;
        sh_res[5] = sq01 / (float)DK - m0 * m1;
        sh_res[6] = sq11 / (float)DK - m1 * m1;
        sh_res[7] = bu1 + np_b[0] + pb_b[0] + pf_b[0];
        sh_res[8] = bu2 + bvB;
        sh_res[9] = bu3 + bvF;
        sh_res[10] = m0;
        sh_res[11] = m1;
    }
    __syncthreads();

    if (t < 12) g_cst[t] = sh_res[t];

    float m0 = sh_res[10], m1 = sh_res[11];
    g_P0[t] = wv0 - m0;
    g_P1[t] = wv1 - m1;

    float a1 = 0.f, a2 = 0.f, a3 = 0.f;
    #pragma unroll
    for (int l = 0; l < HH; ++l) {
        float w = mlp_W[t * HH + l];
        a1 += w * np_W[l];
        a2 += w * sh_u2[l];
        a3 += w * sh_u3[l];
    }
    g_M1[t] = a1;
    g_M2[t] = a2;
    g_M3[t] = a3;
}

// ---------------- counting sort of edges by dst ----------------
__global__ void zero_kernel(int* a, int* b) {
    int i = blockIdx.x * blockDim.x + threadIdx.x;
    if (i < NN) { a[i] = 0; b[i] = 0; }
}

__global__ void hist_kernel(const int* __restrict__ ei, int* __restrict__ cnt) {
    int e = blockIdx.x * blockDim.x + threadIdx.x;
    if (e < NE) atomicAdd(&cnt[ei[NE + e]], 1);
}

__global__ void scan_kernel(const int* __restrict__ cnt, int* __restrict__ ptr, int* __restrict__ cur) {
    __shared__ int buf[1024];
    int t = threadIdx.x;           // 1024 threads, 8 elems each
    int base = t * 8;
    int loc[8]; int s = 0;
    #pragma unroll
    for (int i = 0; i < 8; ++i) { loc[i] = s; s += cnt[base + i]; }
    buf[t] = s;
    __syncthreads();
    // Hillis-Steele inclusive scan
    for (int o = 1; o < 1024; o <<= 1) {
        int v = (t >= o) ? buf[t - o] : 0;
        __syncthreads();
        buf[t] += v;
        __syncthreads();
    }
    int excl = (t == 0) ? 0 : buf[t - 1];
    #pragma unroll
    for (int i = 0; i < 8; ++i) {
        int p = excl + loc[i];
        ptr[base + i] = p;
        cur[base + i] = p;
    }
}

__global__ void scatter_kernel(const int* __restrict__ ei, int* __restrict__ cur, int* __restrict__ srcs) {
    int e = blockIdx.x * blockDim.x + threadIdx.x;
    if (e < NE) {
        int dst = ei[NE + e];
        int pos = atomicAdd(&cur[dst], 1);
        srcs[pos] = ei[e];
    }
}

// ---------------- K_norm: normalize visual rows -> fp16 ----------------
template<int D4>
__global__ void norm_write_kernel(const float* __restrict__ vis, __half2* __restrict__ vn) {
    int warp = (blockIdx.x * blockDim.x + threadIdx.x) >> 5;
    int lane = threadIdx.x & 31;
    if (warp >= NN) return;
    const float4* v = reinterpret_cast<const float4*>(vis) + (size_t)warp * D4;
    float acc = 0.f;
    #pragma unroll 4
    for (int k = lane; k < D4; k += 32) {
        float4 p = v[k];
        acc += p.x * p.x + p.y * p.y + p.z * p.z + p.w * p.w;
    }
    acc = warpSum(acc);
    float rs = rsqrtf(acc + 1e-8f);
    __half2* o = vn + (size_t)warp * (D4 * 2);
    #pragma unroll 4
    for (int k = lane; k < D4; k += 32) {
        float4 p = v[k];
        o[2 * k]     = __floats2half2_rn(p.x * rs, p.y * rs);
        o[2 * k + 1] = __floats2half2_rn(p.z * rs, p.w * rs);
    }
}

// ---------------- K_attn ----------------
__global__ void attn_kernel(const float* __restrict__ x) {
    __shared__ float sa[NG], sb[NG];
    int g = blockIdx.x >> 5;
    int bi = blockIdx.x & 31;
    int t = threadIdx.x;
    int node = g * NG + t;
    sa[t] = x[2 * node];
    sb[t] = x[2 * node + 1];
    __syncthreads();

    float g00 = g_cst[0], g01 = g_cst[1], g10 = g_cst[2], g11 = g_cst[3];
    const float inv = 0.04419417382415922f;
    int warp = t >> 5, lane = t & 31;
    int i = bi * 8 + warp;

    float ai = sa[i], bi2 = sb[i];
    float alpha = (ai * g00 + bi2 * g10) * inv;
    float beta  = (ai * g01 + bi2 * g11) * inv;
    float m = -1e30f;
    #pragma unroll
    for (int j = lane; j < NG; j += 32)
        m = fmaxf(m, alpha * sa[j] + beta * sb[j]);
    #pragma unroll
    for (int o = 16; o; o >>= 1) m = fmaxf(m, __shfl_xor_sync(0xFFFFFFFFu, m, o));
    float s = 0.f, sA = 0.f, sBv = 0.f;
    #pragma unroll
    for (int j = lane; j < NG; j += 32) {
        float e = __expf(alpha * sa[j] + beta * sb[j] - m);
        s += e; sA += e * sa[j]; sBv += e * sb[j];
    }
    s = warpSum(s); sA = warpSum(sA); sBv = warpSum(sBv);
    if (lane == 0) {
        g_c[g * NG + i] = sA / s;
        g_d[g * NG + i] = sBv / s;
    }
}

// ---------------- K_node ----------------
__global__ void node_kernel(const float* __restrict__ ln_g, const float* __restrict__ ln_b,
                            const float* __restrict__ prelu_a, float* __restrict__ out) {
    int warp = (blockIdx.x * blockDim.x + threadIdx.x) >> 5;
    int lane = threadIdx.x & 31;
    if (warp >= NN) return;
    float c = g_c[warp], d = g_d[warp];
    float s00 = g_cst[4], s01 = g_cst[5], s11 = g_cst[6];
    float var = c * c * s00 + 2.f * c * d * s01 + d * d * s11;
    float rstd = rsqrtf(var + EPS);
    float a = prelu_a[0];
    float acc1 = 0.f, acc2 = 0.f, acc3 = 0.f;
    #pragma unroll
    for (int k = lane; k < DK; k += 32) {
        float z = (c * g_P0[k] + d * g_P1[k]) * rstd;
        float tv = z * ln_g[k] + ln_b[k];
        tv = tv >= 0.f ? tv : a * tv;
        acc1 += tv * g_M1[k];
        acc2 += tv * g_M2[k];
        acc3 += tv * g_M3[k];
    }
    acc1 = warpSum(acc1); acc2 = warpSum(acc2); acc3 = warpSum(acc3);
    if (lane == 0) {
        out[warp]  = acc1 + g_cst[7];
        g_sB[warp] = acc2 + g_cst[8];
        g_sF[warp] = acc3 + g_cst[9];
    }
}

// ---------------- K_gather: dst-factorized message accumulate + single dot ----------------
// TPR = threads per row = int4-granules per row (body: 2048h/8 = 256, face: 512h/8 = 64)
// out[dst] += vn[dst] . sum_{e->dst} s[src_e] * vn[src_e]
template<int TPR>
__global__ void gather_dot_kernel(const __half2* __restrict__ vn, const int* __restrict__ srcs,
                                  const int* __restrict__ ptr, const int* __restrict__ cnt,
                                  const float* __restrict__ s, float* __restrict__ out) {
    constexpr int RPB = 256 / TPR;
    __shared__ float red[8];
    int grp = threadIdx.x / TPR;
    int dst = blockIdx.x * RPB + grp;
    int lane = threadIdx.x % TPR;

    int start = ptr[dst];
    int deg   = cnt[dst];
    const int4* base = reinterpret_cast<const int4*>(vn);

    float m[8];
    #pragma unroll
    for (int u = 0; u < 8; ++u) m[u] = 0.f;

    int k = 0;
    for (; k + 2 <= deg; k += 2) {
        int s0 = srcs[start + k];
        int s1 = srcs[start + k + 1];
        float v0 = s[s0];
        float v1 = s[s1];
        int4 p0 = base[(size_t)s0 * TPR + lane];
        int4 p1 = base[(size_t)s1 * TPR + lane];
        const __half2* h0 = reinterpret_cast<const __half2*>(&p0);
        const __half2* h1 = reinterpret_cast<const __half2*>(&p1);
        #pragma unroll
        for (int u = 0; u < 4; ++u) {
            float2 f0 = __half22float2(h0[u]);
            float2 f1 = __half22float2(h1[u]);
            m[2 * u]     += v0 * f0.x + v1 * f1.x;
            m[2 * u + 1] += v0 * f0.y + v1 * f1.y;
        }
    }
    if (k < deg) {
        int s0 = srcs[start + k];
        float v0 = s[s0];
        int4 p0 = base[(size_t)s0 * TPR + lane];
        const __half2* h0 = reinterpret_cast<const __half2*>(&p0);
        #pragma unroll
        for (int u = 0; u < 4; ++u) {
            float2 f0 = __half22float2(h0[u]);
            m[2 * u]     += v0 * f0.x;
            m[2 * u + 1] += v0 * f0.y;
        }
    }

    // dot with vn[dst]
    int4 q = base[(size_t)dst * TPR + lane];
    const __half2* hq = reinterpret_cast<const __half2*>(&q);
    float acc = 0.f;
    #pragma unroll
    for (int u = 0; u < 4; ++u) {
        float2 fq = __half22float2(hq[u]);
        acc += m[2 * u] * fq.x + m[2 * u + 1] * fq.y;
    }
    acc = warpSum(acc);
    int w = threadIdx.x >> 5;
    if ((threadIdx.x & 31) == 0) red[w] = acc;
    __syncthreads();
    if (lane == 0) {
        constexpr int WPG = TPR / 32;
        int w0 = grp * WPG;
        float tot = 0.f;
        #pragma unroll
        for (int i = 0; i < WPG; ++i) tot += red[w0 + i];
        atomicAdd(&out[dst], tot);
    }
}

// ---------------- launch ----------------
extern "C" void kernel_launch(void* const* d_in, const int* in_sizes, int n_in,
                              void* d_out, int out_size) {
    const float* x           = (const float*)d_in[0];
    const float* visual_body = (const float*)d_in[1];
    const float* visual_face = (const float*)d_in[2];
    const float* Wq          = (const float*)d_in[3];
    const float* Wk          = (const float*)d_in[4];
    const float* Wv          = (const float*)d_in[5];
    const float* ln_g        = (const float*)d_in[6];
    const float* ln_b        = (const float*)d_in[7];
    const float* prelu_a     = (const float*)d_in[8];
    const float* mlp_W       = (const float*)d_in[9];
    const float* mlp_b       = (const float*)d_in[10];
    const float* np_W        = (const float*)d_in[11];
    const float* np_b        = (const float*)d_in[12];
    const float* body_W      = (const float*)d_in[13];
    const float* body_b      = (const float*)d_in[14];
    const float* face_W      = (const float*)d_in[15];
    const float* face_b      = (const float*)d_in[16];
    const float* pb_W        = (const float*)d_in[17];
    const float* pb_b        = (const float*)d_in[18];
    const float* pf_W        = (const float*)d_in[19];
    const float* pf_b        = (const float*)d_in[20];
    const int*   ei_body     = (const int*)d_in[21];
    const int*   ei_face     = (const int*)d_in[22];
    float* out = (float*)d_out;

    __half2* d_vnB; cudaGetSymbolAddress((void**)&d_vnB, g_vnB);
    __half2* d_vnF; cudaGetSymbolAddress((void**)&d_vnF, g_vnF);
    float* d_sB;  cudaGetSymbolAddress((void**)&d_sB, g_sB);
    float* d_sF;  cudaGetSymbolAddress((void**)&d_sF, g_sF);
    int *d_cntB, *d_cntF, *d_ptrB, *d_ptrF, *d_curB, *d_curF, *d_srcB, *d_srcF;
    cudaGetSymbolAddress((void**)&d_cntB, g_cntB);
    cudaGetSymbolAddress((void**)&d_cntF, g_cntF);
    cudaGetSymbolAddress((void**)&d_ptrB, g_ptrB);
    cudaGetSymbolAddress((void**)&d_ptrF, g_ptrF);
    cudaGetSymbolAddress((void**)&d_curB, g_curB);
    cudaGetSymbolAddress((void**)&d_curF, g_curF);
    cudaGetSymbolAddress((void**)&d_srcB, g_srcB);
    cudaGetSymbolAddress((void**)&d_srcF, g_srcF);

    precompute_kernel<<<1, 512>>>(Wq, Wk, Wv, mlp_W, mlp_b, np_W, np_b,
                                  body_W, body_b, face_W, face_b,
                                  pb_W, pb_b, pf_W, pf_b);

    // counting sort of edges by dst
    zero_kernel<<<NN / 1024, 1024>>>(d_cntB, d_cntF);
    hist_kernel<<<NE / 256, 256>>>(ei_body, d_cntB);
    hist_kernel<<<NE / 256, 256>>>(ei_face, d_cntF);
    scan_kernel<<<1, 1024>>>(d_cntB, d_ptrB, d_curB);
    scan_kernel<<<1, 1024>>>(d_cntF, d_ptrF, d_curF);
    scatter_kernel<<<NE / 256, 256>>>(ei_body, d_curB, d_srcB);
    scatter_kernel<<<NE / 256, 256>>>(ei_face, d_curF, d_srcF);

    // normalize visuals to fp16
    norm_write_kernel<VB / 4><<<(NN * 32) / 256, 256>>>(visual_body, d_vnB);
    norm_write_kernel<VF / 4><<<(NN * 32) / 256, 256>>>(visual_face, d_vnF);

    // attention
    attn_kernel<<<NB * 32, NG>>>(x);

    // node stage (writes out base + per-node payloads)
    node_kernel<<<(NN * 32) / 256, 256>>>(ln_g, ln_b, prelu_a, out);

    // dst-factorized edge reductions
    gather_dot_kernel<256><<<NN, 256>>>(d_vnB, d_srcB, d_ptrB, d_cntB, d_sB, out);
    gather_dot_kernel<64><<<NN / 4, 256>>>(d_vnF, d_srcF, d_ptrF, d_cntF, d_sF, out);
}

// round 4
// speedup vs baseline: 1.2205x; 1.2205x over previous
#include <cuda_runtime.h>
#include <cuda_fp16.h>
#include <math.h>

#define NN 8192
#define NB 32
#define NG 256
#define NE 65536
#define DK 512
#define HH 32
#define VB 2048
#define VF 512
#define EPS 1e-5f

// ---------------- device scratch ----------------
__device__ float g_sB[NN], g_sF[NN];
__device__ __half2 g_vnB[NN * VB / 2];   // normalized visual_body fp16 (32 MB)
__device__ __half2 g_vnF[NN * VF / 2];   // normalized visual_face fp16 (8 MB)
__device__ float g_P0[DK], g_P1[DK];
__device__ float g_M1[DK], g_M2[DK], g_M3[DK];
__device__ float g_cst[12];
// sort scratch
__device__ int g_cntB[NN], g_cntF[NN];
__device__ int g_curB[NN], g_curF[NN];
__device__ int2 g_edB[NE], g_edF[NE];    // dst-sorted (src,dst) pairs

// ---------------- helpers ----------------
__device__ __forceinline__ float blockReduceSum(float v, float* red) {
    int t = threadIdx.x;
    red[t] = v;
    __syncthreads();
    for (int s = blockDim.x >> 1; s > 0; s >>= 1) {
        if (t < s) red[t] += red[t + s];
        __syncthreads();
    }
    float r = red[0];
    __syncthreads();
    return r;
}

__device__ __forceinline__ float warpSum(float v) {
    #pragma unroll
    for (int o = 16; o; o >>= 1) v += __shfl_xor_sync(0xFFFFFFFFu, v, o);
    return v;
}

// ---------------- K0: precompute constants ----------------
__global__ void precompute_kernel(
    const float* __restrict__ Wq, const float* __restrict__ Wk, const float* __restrict__ Wv,
    const float* __restrict__ mlp_W, const float* __restrict__ mlp_b,
    const float* __restrict__ np_W, const float* __restrict__ np_b,
    const float* __restrict__ body_W, const float* __restrict__ body_b,
    const float* __restrict__ face_W, const float* __restrict__ face_b,
    const float* __restrict__ pb_W, const float* __restrict__ pb_b,
    const float* __restrict__ pf_W, const float* __restrict__ pf_b)
{
    __shared__ float red[512];
    __shared__ float sh_u2[HH], sh_u3[HH];
    __shared__ float sh_res[12];
    int t = threadIdx.x;   // 512 threads

    if (t < HH) {
        float a2 = 0.f, a3 = 0.f;
        #pragma unroll
        for (int j = 0; j < HH; ++j) {
            a2 += body_W[t * HH + j] * pb_W[j];
            a3 += face_W[t * HH + j] * pf_W[j];
        }
        sh_u2[t] = a2;
        sh_u3[t] = a3;
    }
    __syncthreads();

    float wq0 = Wq[t], wq1 = Wq[DK + t];
    float wk0 = Wk[t], wk1 = Wk[DK + t];
    float wv0 = Wv[t], wv1 = Wv[DK + t];

    float g00 = blockReduceSum(wq0 * wk0, red);
    float g01 = blockReduceSum(wq0 * wk1, red);
    float g10 = blockReduceSum(wq1 * wk0, red);
    float g11 = blockReduceSum(wq1 * wk1, red);
    float sum0 = blockReduceSum(wv0, red);
    float sum1 = blockReduceSum(wv1, red);
    float sq00 = blockReduceSum(wv0 * wv0, red);
    float sq01 = blockReduceSum(wv0 * wv1, red);
    float sq11 = blockReduceSum(wv1 * wv1, red);
    float bu1 = blockReduceSum(t < HH ? mlp_b[t] * np_W[t] : 0.f, red);
    float bu2 = blockReduceSum(t < HH ? mlp_b[t] * sh_u2[t] : 0.f, red);
    float bu3 = blockReduceSum(t < HH ? mlp_b[t] * sh_u3[t] : 0.f, red);
    float bvB = blockReduceSum(t < HH ? body_b[t] * pb_W[t] : 0.f, red);
    float bvF = blockReduceSum(t < HH ? face_b[t] * pf_W[t] : 0.f, red);

    if (t == 0) {
        float m0 = sum0 / (float)DK, m1 = sum1 / (float)DK;
        sh_res[0] = g00; sh_res[1] = g01; sh_res[2] = g10; sh_res[3] = g11;
        sh_res[4] = sq00 / (float)DK - m0 * m0;
        sh_res[5] = sq01 / (float)DK - m0 * m1;
        sh_res[6] = sq11 / (float)DK - m1 * m1;
        sh_res[7] = bu1 + np_b[0] + pb_b[0] + pf_b[0];
        sh_res[8] = bu2 + bvB;
        sh_res[9] = bu3 + bvF;
        sh_res[10] = m0;
        sh_res[11] = m1;
    }
    __syncthreads();

    if (t < 12) g_cst[t] = sh_res[t];

    float m0 = sh_res[10], m1 = sh_res[11];
    g_P0[t] = wv0 - m0;
    g_P1[t] = wv1 - m1;

    float a1 = 0.f, a2 = 0.f, a3 = 0.f;
    #pragma unroll
    for (int l = 0; l < HH; ++l) {
        float w = mlp_W[t * HH + l];
        a1 += w * np_W[l];
        a2 += w * sh_u2[l];
        a3 += w * sh_u3[l];
    }
    g_M1[t] = a1;
    g_M2[t] = a2;
    g_M3[t] = a3;
}

// ---------------- counting sort by dst (both graphs) ----------------
__global__ void zero_kernel(int* a, int* b) {
    int i = blockIdx.x * blockDim.x + threadIdx.x;
    if (i < NN) { a[i] = 0; b[i] = 0; }
}

__global__ void hist_kernel(const int* __restrict__ eiB, const int* __restrict__ eiF,
                            int* __restrict__ cntB, int* __restrict__ cntF) {
    int e = blockIdx.x * blockDim.x + threadIdx.x;
    if (e < NE) atomicAdd(&cntB[eiB[NE + e]], 1);
    else        atomicAdd(&cntF[eiF[e]], 1);  // e-NE+NE = e
}

__global__ void scan_kernel(const int* __restrict__ cntB, int* __restrict__ curB,
                            const int* __restrict__ cntF, int* __restrict__ curF) {
    __shared__ int buf[1024];
    int t = threadIdx.x;           // 1024 threads, 8 elems each
    const int* cnt = blockIdx.x ? cntF : cntB;
    int* cur = blockIdx.x ? curF : curB;
    int base = t * 8;
    int loc[8]; int s = 0;
    #pragma unroll
    for (int i = 0; i < 8; ++i) { loc[i] = s; s += cnt[base + i]; }
    buf[t] = s;
    __syncthreads();
    for (int o = 1; o < 1024; o <<= 1) {
        int v = (t >= o) ? buf[t - o] : 0;
        __syncthreads();
        buf[t] += v;
        __syncthreads();
    }
    int excl = (t == 0) ? 0 : buf[t - 1];
    #pragma unroll
    for (int i = 0; i < 8; ++i) cur[base + i] = excl + loc[i];
}

__global__ void scatter_kernel(const int* __restrict__ eiB, const int* __restrict__ eiF,
                               int* __restrict__ curB, int* __restrict__ curF,
                               int2* __restrict__ edB, int2* __restrict__ edF) {
    int e = blockIdx.x * blockDim.x + threadIdx.x;
    if (e < NE) {
        int src = eiB[e], dst = eiB[NE + e];
        int pos = atomicAdd(&curB[dst], 1);
        edB[pos] = make_int2(src, dst);
    } else {
        e -= NE;
        int src = eiF[e], dst = eiF[NE + e];
        int pos = atomicAdd(&curF[dst], 1);
        edF[pos] = make_int2(src, dst);
    }
}

// ---------------- K_norm: normalize visual rows -> fp16 (both tensors) ----------------
template<int D4>
__device__ __forceinline__ void norm_row(const float* vis, __half2* vn, int row, int lane) {
    const float4* v = reinterpret_cast<const float4*>(vis) + (size_t)row * D4;
    float acc = 0.f;
    #pragma unroll 4
    for (int k = lane; k < D4; k += 32) {
        float4 p = v[k];
        acc += p.x * p.x + p.y * p.y + p.z * p.z + p.w * p.w;
    }
    acc = warpSum(acc);
    float rs = rsqrtf(acc + 1e-8f);
    __half2* o = vn + (size_t)row * (D4 * 2);
    #pragma unroll 4
    for (int k = lane; k < D4; k += 32) {
        float4 p = v[k];
        o[2 * k]     = __floats2half2_rn(p.x * rs, p.y * rs);
        o[2 * k + 1] = __floats2half2_rn(p.z * rs, p.w * rs);
    }
}

__global__ void norm_kernel(const float* __restrict__ visB, const float* __restrict__ visF) {
    int warp = (blockIdx.x * blockDim.x + threadIdx.x) >> 5;
    int lane = threadIdx.x & 31;
    if (warp < NN) norm_row<VB / 4>(visB, g_vnB, warp, lane);
    else           norm_row<VF / 4>(visF, g_vnF, warp - NN, lane);
}

// ---------------- K_attn_node: rank-2 attention + LN/PReLU/projections, fused ----------------
// grid = NB*32 blocks, 256 threads; warp w of block (g,bi) owns node g*NG + bi*8 + w
__global__ void attn_node_kernel(const float* __restrict__ x,
                                 const float* __restrict__ ln_g, const float* __restrict__ ln_b,
                                 const float* __restrict__ prelu_a, float* __restrict__ out) {
    __shared__ float sa[NG], sb[NG];
    int g = blockIdx.x >> 5;
    int bi = blockIdx.x & 31;
    int t = threadIdx.x;
    int node = g * NG + t;
    sa[t] = x[2 * node];
    sb[t] = x[2 * node + 1];
    __syncthreads();

    float g00 = g_cst[0], g01 = g_cst[1], g10 = g_cst[2], g11 = g_cst[3];
    const float inv = 0.04419417382415922f;
    int warp = t >> 5, lane = t & 31;
    int i = bi * 8 + warp;

    float ai = sa[i], bi2 = sb[i];
    float alpha = (ai * g00 + bi2 * g10) * inv;
    float beta  = (ai * g01 + bi2 * g11) * inv;
    float m = -1e30f;
    #pragma unroll
    for (int j = lane; j < NG; j += 32)
        m = fmaxf(m, alpha * sa[j] + beta * sb[j]);
    #pragma unroll
    for (int o = 16; o; o >>= 1) m = fmaxf(m, __shfl_xor_sync(0xFFFFFFFFu, m, o));
    float s = 0.f, sA = 0.f, sBv = 0.f;
    #pragma unroll
    for (int j = lane; j < NG; j += 32) {
        float e = __expf(alpha * sa[j] + beta * sb[j] - m);
        s += e; sA += e * sa[j]; sBv += e * sb[j];
    }
    s = warpSum(s); sA = warpSum(sA); sBv = warpSum(sBv);
    float c = sA / s, d = sBv / s;

    // node stage in-register
    float s00 = g_cst[4], s01 = g_cst[5], s11 = g_cst[6];
    float var = c * c * s00 + 2.f * c * d * s01 + d * d * s11;
    float rstd = rsqrtf(var + EPS);
    float a = prelu_a[0];
    float acc1 = 0.f, acc2 = 0.f, acc3 = 0.f;
    #pragma unroll
    for (int k = lane; k < DK; k += 32) {
        float z = (c * g_P0[k] + d * g_P1[k]) * rstd;
        float tv = z * ln_g[k] + ln_b[k];
        tv = tv >= 0.f ? tv : a * tv;
        acc1 += tv * g_M1[k];
        acc2 += tv * g_M2[k];
        acc3 += tv * g_M3[k];
    }
    acc1 = warpSum(acc1); acc2 = warpSum(acc2); acc3 = warpSum(acc3);
    if (lane == 0) {
        int n = g * NG + i;
        out[n]  = acc1 + g_cst[7];
        g_sB[n] = acc2 + g_cst[8];
        g_sF[n] = acc3 + g_cst[9];
    }
}

// ---------------- K_edge: warp per edge over dst-sorted edges ----------------
// D8 = int4-granules per row (body 256, face 64). dst rows L1-hit via sorting.
template<int D8>
__global__ void edge_kernel(const __half2* __restrict__ vn, const int2* __restrict__ ed,
                            const float* __restrict__ s, float* __restrict__ out) {
    int warp = (blockIdx.x * blockDim.x + threadIdx.x) >> 5;
    int lane = threadIdx.x & 31;
    if (warp >= NE) return;
    int2 e = ed[warp];
    int src = e.x, dst = e.y;
    const int4* a = reinterpret_cast<const int4*>(vn) + (size_t)src * D8;
    const int4* b = reinterpret_cast<const int4*>(vn) + (size_t)dst * D8;
    float acc = 0.f;
    #pragma unroll
    for (int k = lane; k < D8; k += 32) {
        int4 pa = a[k];
        int4 pb = b[k];
        const __half2* ha = reinterpret_cast<const __half2*>(&pa);
        const __half2* hb = reinterpret_cast<const __half2*>(&pb);
        #pragma unroll
        for (int u = 0; u < 4; ++u) {
            float2 fa = __half22float2(ha[u]);
            float2 fb = __half22float2(hb[u]);
            acc += fa.x * fb.x + fa.y * fb.y;
        }
    }
    acc = warpSum(acc);
    if (lane == 0) {
        atomicAdd(&out[dst], acc * s[src]);
    }
}

// ---------------- launch ----------------
extern "C" void kernel_launch(void* const* d_in, const int* in_sizes, int n_in,
                              void* d_out, int out_size) {
    const float* x           = (const float*)d_in[0];
    const float* visual_body = (const float*)d_in[1];
    const float* visual_face = (const float*)d_in[2];
    const float* Wq          = (const float*)d_in[3];
    const float* Wk          = (const float*)d_in[4];
    const float* Wv          = (const float*)d_in[5];
    const float* ln_g        = (const float*)d_in[6];
    const float* ln_b        = (const float*)d_in[7];
    const float* prelu_a     = (const float*)d_in[8];
    const float* mlp_W       = (const float*)d_in[9];
    const float* mlp_b       = (const float*)d_in[10];
    const float* np_W        = (const float*)d_in[11];
    const float* np_b        = (const float*)d_in[12];
    const float* body_W      = (const float*)d_in[13];
    const float* body_b      = (const float*)d_in[14];
    const float* face_W      = (const float*)d_in[15];
    const float* face_b      = (const float*)d_in[16];
    const float* pb_W        = (const float*)d_in[17];
    const float* pb_b        = (const float*)d_in[18];
    const float* pf_W        = (const float*)d_in[19];
    const float* pf_b        = (const float*)d_in[20];
    const int*   ei_body     = (const int*)d_in[21];
    const int*   ei_face     = (const int*)d_in[22];
    float* out = (float*)d_out;

    __half2* d_vnB; cudaGetSymbolAddress((void**)&d_vnB, g_vnB);
    __half2* d_vnF; cudaGetSymbolAddress((void**)&d_vnF, g_vnF);
    float* d_sB;  cudaGetSymbolAddress((void**)&d_sB, g_sB);
    float* d_sF;  cudaGetSymbolAddress((void**)&d_sF, g_sF);
    int *d_cntB, *d_cntF, *d_curB, *d_curF;
    int2 *d_edB, *d_edF;
    cudaGetSymbolAddress((void**)&d_cntB, g_cntB);
    cudaGetSymbolAddress((void**)&d_cntF, g_cntF);
    cudaGetSymbolAddress((void**)&d_curB, g_curB);
    cudaGetSymbolAddress((void**)&d_curF, g_curF);
    cudaGetSymbolAddress((void**)&d_edB, g_edB);
    cudaGetSymbolAddress((void**)&d_edF, g_edF);

    precompute_kernel<<<1, 512>>>(Wq, Wk, Wv, mlp_W, mlp_b, np_W, np_b,
                                  body_W, body_b, face_W, face_b,
                                  pb_W, pb_b, pf_W, pf_b);

    // counting sort by dst (both edge lists)
    zero_kernel<<<NN / 1024, 1024>>>(d_cntB, d_cntF);
    hist_kernel<<<2 * NE / 256, 256>>>(ei_body, ei_face, d_cntB, d_cntF);
    scan_kernel<<<2, 1024>>>(d_cntB, d_curB, d_cntF, d_curF);
    scatter_kernel<<<2 * NE / 256, 256>>>(ei_body, ei_face, d_curB, d_curF, d_edB, d_edF);

    // normalize visuals to fp16 (body + face in one kernel)
    norm_kernel<<<(2 * NN * 32) / 256, 256>>>(visual_body, visual_face);

    // fused attention + node stage
    attn_node_kernel<<<NB * 32, NG>>>(x, ln_g, ln_b, prelu_a, out);

    // edge reductions over dst-sorted edges
    edge_kernel<VB / 8><<<(NE * 32) / 256, 256>>>(d_vnB, d_edB, d_sB, out);
    edge_kernel<VF / 8><<<(NE * 32) / 256, 256>>>(d_vnF, d_edF, d_sF, out);
}

// round 5
// speedup vs baseline: 1.5455x; 1.2663x over previous
#include <cuda_runtime.h>
#include <cuda_fp16.h>
#include <math.h>

#define NN 8192
#define NB 32
#define NG 256
#define NE 65536
#define DK 512
#define HH 32
#define VB 2048
#define VF 512
#define EPS 1e-5f

// ---------------- device scratch ----------------
__device__ float g_sB[NN], g_sF[NN];
__device__ __half2 g_vnB[NN * VB / 2];   // normalized visual_body fp16 (32 MB)
__device__ __half2 g_vnF[NN * VF / 2];   // normalized visual_face fp16 (8 MB)
__device__ float g_P0[DK], g_P1[DK];
__device__ float g_M1[DK], g_M2[DK], g_M3[DK];
__device__ float g_cst[12];

// ---------------- helpers ----------------
__device__ __forceinline__ float blockReduceSum(float v, float* red) {
    int t = threadIdx.x;
    red[t] = v;
    __syncthreads();
    for (int s = blockDim.x >> 1; s > 0; s >>= 1) {
        if (t < s) red[t] += red[t + s];
        __syncthreads();
    }
    float r = red[0];
    __syncthreads();
    return r;
}

__device__ __forceinline__ float warpSum(float v) {
    #pragma unroll
    for (int o = 16; o; o >>= 1) v += __shfl_xor_sync(0xFFFFFFFFu, v, o);
    return v;
}

// ---------------- K0: precompute constants ----------------
__global__ void precompute_kernel(
    const float* __restrict__ Wq, const float* __restrict__ Wk, const float* __restrict__ Wv,
    const float* __restrict__ mlp_W, const float* __restrict__ mlp_b,
    const float* __restrict__ np_W, const float* __restrict__ np_b,
    const float* __restrict__ body_W, const float* __restrict__ body_b,
    const float* __restrict__ face_W, const float* __restrict__ face_b,
    const float* __restrict__ pb_W, const float* __restrict__ pb_b,
    const float* __restrict__ pf_W, const float* __restrict__ pf_b)
{
    __shared__ float red[512];
    __shared__ float sh_u2[HH], sh_u3[HH];
    __shared__ float sh_res[12];
    int t = threadIdx.x;   // 512 threads

    if (t < HH) {
        float a2 = 0.f, a3 = 0.f;
        #pragma unroll
        for (int j = 0; j < HH; ++j) {
            a2 += body_W[t * HH + j] * pb_W[j];
            a3 += face_W[t * HH + j] * pf_W[j];
        }
        sh_u2[t] = a2;
        sh_u3[t] = a3;
    }
    __syncthreads();

    float wq0 = Wq[t], wq1 = Wq[DK + t];
    float wk0 = Wk[t], wk1 = Wk[DK + t];
    float wv0 = Wv[t], wv1 = Wv[DK + t];

    float g00 = blockReduceSum(wq0 * wk0, red);
    float g01 = blockReduceSum(wq0 * wk1, red);
    float g10 = blockReduceSum(wq1 * wk0, red);
    float g11 = blockReduceSum(wq1 * wk1, red);
    float sum0 = blockReduceSum(wv0, red);
    float sum1 = blockReduceSum(wv1, red);
    float sq00 = blockReduceSum(wv0 * wv0, red);
    float sq01 = blockReduceSum(wv0 * wv1, red);
    float sq11 = blockReduceSum(wv1 * wv1, red);
    float bu1 = blockReduceSum(t < HH ? mlp_b[t] * np_W[t] : 0.f, red);
    float bu2 = blockReduceSum(t < HH ? mlp_b[t] * sh_u2[t] : 0.f, red);
    float bu3 = blockReduceSum(t < HH ? mlp_b[t] * sh_u3[t] : 0.f, red);
    float bvB = blockReduceSum(t < HH ? body_b[t] * pb_W[t] : 0.f, red);
    float bvF = blockReduceSum(t < HH ? face_b[t] * pf_W[t] : 0.f, red);

    if (t == 0) {
        float m0 = sum0 / (float)DK, m1 = sum1 / (float)DK;
        sh_res[0] = g00; sh_res[1] = g01; sh_res[2] = g10; sh_res[3] = g11;
        sh_res[4] = sq00 / (float)DK - m0 * m0;
        sh_res[5] = sq01 / (float)DK - m0 * m1;
        sh_res[6] = sq11 / (float)DK - m1 * m1;
        sh_res[7] = bu1 + np_b[0] + pb_b[0] + pf_b[0];
        sh_res[8] = bu2 + bvB;
        sh_res[9] = bu3 + bvF;
        sh_res[10] = m0;
        sh_res[11] = m1;
    }
    __syncthreads();

    if (t < 12) g_cst[t] = sh_res[t];

    float m0 = sh_res[10], m1 = sh_res[11];
    g_P0[t] = wv0 - m0;
    g_P1[t] = wv1 - m1;

    float a1 = 0.f, a2 = 0.f, a3 = 0.f;
    #pragma unroll
    for (int l = 0; l < HH; ++l) {
        float w = mlp_W[t * HH + l];
        a1 += w * np_W[l];
        a2 += w * sh_u2[l];
        a3 += w * sh_u3[l];
    }
    g_M1[t] = a1;
    g_M2[t] = a2;
    g_M3[t] = a3;
}

// ---------------- K_norm: normalize visual rows -> fp16 (both tensors) ----------------
template<int D4>
__device__ __forceinline__ void norm_row(const float* vis, __half2* vn, int row, int lane) {
    const float4* v = reinterpret_cast<const float4*>(vis) + (size_t)row * D4;
    float acc = 0.f;
    #pragma unroll 4
    for (int k = lane; k < D4; k += 32) {
        float4 p = v[k];
        acc += p.x * p.x + p.y * p.y + p.z * p.z + p.w * p.w;
    }
    acc = warpSum(acc);
    float rs = rsqrtf(acc + 1e-8f);
    __half2* o = vn + (size_t)row * (D4 * 2);
    #pragma unroll 4
    for (int k = lane; k < D4; k += 32) {
        float4 p = v[k];
        o[2 * k]     = __floats2half2_rn(p.x * rs, p.y * rs);
        o[2 * k + 1] = __floats2half2_rn(p.z * rs, p.w * rs);
    }
}

__global__ void norm_kernel(const float* __restrict__ visB, const float* __restrict__ visF) {
    int warp = (blockIdx.x * blockDim.x + threadIdx.x) >> 5;
    int lane = threadIdx.x & 31;
    if (warp < NN) norm_row<VB / 4>(visB, g_vnB, warp, lane);
    else           norm_row<VF / 4>(visF, g_vnF, warp - NN, lane);
}

// ---------------- K_attn_node: rank-2 attention + LN/PReLU/projections, fused ----------------
__global__ void attn_node_kernel(const float* __restrict__ x,
                                 const float* __restrict__ ln_g, const float* __restrict__ ln_b,
                                 const float* __restrict__ prelu_a, float* __restrict__ out) {
    __shared__ float sa[NG], sb[NG];
    int g = blockIdx.x >> 5;
    int bi = blockIdx.x & 31;
    int t = threadIdx.x;
    int node = g * NG + t;
    sa[t] = x[2 * node];
    sb[t] = x[2 * node + 1];
    __syncthreads();

    float g00 = g_cst[0], g01 = g_cst[1], g10 = g_cst[2], g11 = g_cst[3];
    const float inv = 0.04419417382415922f;
    int warp = t >> 5, lane = t & 31;
    int i = bi * 8 + warp;

    float ai = sa[i], bi2 = sb[i];
    float alpha = (ai * g00 + bi2 * g10) * inv;
    float beta  = (ai * g01 + bi2 * g11) * inv;
    float m = -1e30f;
    #pragma unroll
    for (int j = lane; j < NG; j += 32)
        m = fmaxf(m, alpha * sa[j] + beta * sb[j]);
    #pragma unroll
    for (int o = 16; o; o >>= 1) m = fmaxf(m, __shfl_xor_sync(0xFFFFFFFFu, m, o));
    float s = 0.f, sA = 0.f, sBv = 0.f;
    #pragma unroll
    for (int j = lane; j < NG; j += 32) {
        float e = __expf(alpha * sa[j] + beta * sb[j] - m);
        s += e; sA += e * sa[j]; sBv += e * sb[j];
    }
    s = warpSum(s); sA = warpSum(sA); sBv = warpSum(sBv);
    float c = sA / s, d = sBv / s;

    float s00 = g_cst[4], s01 = g_cst[5], s11 = g_cst[6];
    float var = c * c * s00 + 2.f * c * d * s01 + d * d * s11;
    float rstd = rsqrtf(var + EPS);
    float a = prelu_a[0];
    float acc1 = 0.f, acc2 = 0.f, acc3 = 0.f;
    #pragma unroll
    for (int k = lane; k < DK; k += 32) {
        float z = (c * g_P0[k] + d * g_P1[k]) * rstd;
        float tv = z * ln_g[k] + ln_b[k];
        tv = tv >= 0.f ? tv : a * tv;
        acc1 += tv * g_M1[k];
        acc2 += tv * g_M2[k];
        acc3 += tv * g_M3[k];
    }
    acc1 = warpSum(acc1); acc2 = warpSum(acc2); acc3 = warpSum(acc3);
    if (lane == 0) {
        int n = g * NG + i;
        out[n]  = acc1 + g_cst[7];
        g_sB[n] = acc2 + g_cst[8];
        g_sF[n] = acc3 + g_cst[9];
    }
}

// ---------------- K_edge: merged body+face, deep prefetch ----------------
// Body: warp per edge, 8+8 int4 prefetched per lane (MLP=16).
// Face: half-warp per edge (2 edges/warp), 4+4 int4 prefetched (MLP=8).
// grid: first BODY_BLOCKS blocks do body, rest do face. 128 threads/block.
#define EDGE_TPB 128
#define BODY_WARPS NE                 // 65536 warps
#define FACE_WARPS (NE / 2)           // 32768 warps
#define BODY_BLOCKS (BODY_WARPS * 32 / EDGE_TPB)   // 16384
#define FACE_BLOCKS (FACE_WARPS * 32 / EDGE_TPB)   // 8192

__global__ void edge_kernel(const int* __restrict__ eiB, const int* __restrict__ eiF,
                            float* __restrict__ out) {
    int gw = (blockIdx.x * EDGE_TPB + threadIdx.x) >> 5;
    int lane = threadIdx.x & 31;

    if (gw < BODY_WARPS) {
        int e = gw;
        int src = eiB[e], dst = eiB[NE + e];
        const int4* a = reinterpret_cast<const int4*>(g_vnB) + (size_t)src * (VB / 8) + lane;
        const int4* b = reinterpret_cast<const int4*>(g_vnB) + (size_t)dst * (VB / 8) + lane;
        int4 ra[8], rb[8];
        #pragma unroll
        for (int i = 0; i < 8; ++i) ra[i] = a[i * 32];
        #pragma unroll
        for (int i = 0; i < 8; ++i) rb[i] = b[i * 32];
        float acc0 = 0.f, acc1 = 0.f;
        #pragma unroll
        for (int i = 0; i < 8; ++i) {
            const __half2* ha = reinterpret_cast<const __half2*>(&ra[i]);
            const __half2* hb = reinterpret_cast<const __half2*>(&rb[i]);
            #pragma unroll
            for (int u = 0; u < 4; ++u) {
                float2 fa = __half22float2(ha[u]);
                float2 fb = __half22float2(hb[u]);
                acc0 += fa.x * fb.x;
                acc1 += fa.y * fb.y;
            }
        }
        float acc = warpSum(acc0 + acc1);
        if (lane == 0) atomicAdd(&out[dst], acc * g_sB[src]);
    } else {
        int e = (gw - BODY_WARPS) * 2 + (lane >> 4);
        int hl = lane & 15;
        int src = eiF[e], dst = eiF[NE + e];
        const int4* a = reinterpret_cast<const int4*>(g_vnF) + (size_t)src * (VF / 8) + hl;
        const int4* b = reinterpret_cast<const int4*>(g_vnF) + (size_t)dst * (VF / 8) + hl;
        int4 ra[4], rb[4];
        #pragma unroll
        for (int i = 0; i < 4; ++i) ra[i] = a[i * 16];
        #pragma unroll
        for (int i = 0; i < 4; ++i) rb[i] = b[i * 16];
        float acc0 = 0.f, acc1 = 0.f;
        #pragma unroll
        for (int i = 0; i < 4; ++i) {
            const __half2* ha = reinterpret_cast<const __half2*>(&ra[i]);
            const __half2* hb = reinterpret_cast<const __half2*>(&rb[i]);
            #pragma unroll
            for (int u = 0; u < 4; ++u) {
                float2 fa = __half22float2(ha[u]);
                float2 fb = __half22float2(hb[u]);
                acc0 += fa.x * fb.x;
                acc1 += fa.y * fb.y;
            }
        }
        float acc = acc0 + acc1;
        #pragma unroll
        for (int o = 8; o; o >>= 1) acc += __shfl_xor_sync(0xFFFFFFFFu, acc, o);
        if (hl == 0) atomicAdd(&out[dst], acc * g_sF[src]);
    }
}

// ---------------- launch ----------------
extern "C" void kernel_launch(void* const* d_in, const int* in_sizes, int n_in,
                              void* d_out, int out_size) {
    const float* x           = (const float*)d_in[0];
    const float* visual_body = (const float*)d_in[1];
    const float* visual_face = (const float*)d_in[2];
    const float* Wq          = (const float*)d_in[3];
    const float* Wk          = (const float*)d_in[4];
    const float* Wv          = (const float*)d_in[5];
    const float* ln_g        = (const float*)d_in[6];
    const float* ln_b        = (const float*)d_in[7];
    const float* prelu_a     = (const float*)d_in[8];
    const float* mlp_W       = (const float*)d_in[9];
    const float* mlp_b       = (const float*)d_in[10];
    const float* np_W        = (const float*)d_in[11];
    const float* np_b        = (const float*)d_in[12];
    const float* body_W      = (const float*)d_in[13];
    const float* body_b      = (const float*)d_in[14];
    const float* face_W      = (const float*)d_in[15];
    const float* face_b      = (const float*)d_in[16];
    const float* pb_W        = (const float*)d_in[17];
    const float* pb_b        = (const float*)d_in[18];
    const float* pf_W        = (const float*)d_in[19];
    const float* pf_b        = (const float*)d_in[20];
    const int*   ei_body     = (const int*)d_in[21];
    const int*   ei_face     = (const int*)d_in[22];
    float* out = (float*)d_out;

    precompute_kernel<<<1, 512>>>(Wq, Wk, Wv, mlp_W, mlp_b, np_W, np_b,
                                  body_W, body_b, face_W, face_b,
                                  pb_W, pb_b, pf_W, pf_b);

    // normalize visuals to fp16 (body + face in one kernel)
    norm_kernel<<<(2 * NN * 32) / 256, 256>>>(visual_body, visual_face);

    // fused attention + node stage (writes out base + per-node payloads)
    attn_node_kernel<<<NB * 32, NG>>>(x, ln_g, ln_b, prelu_a, out);

    // merged edge reduction, deep prefetch
    edge_kernel<<<BODY_BLOCKS + FACE_BLOCKS, EDGE_TPB>>>(ei_body, ei_face, out);
}

// round 6
// speedup vs baseline: 1.6777x; 1.0855x over previous
#include <cuda_runtime.h>
#include <cuda_fp16.h>
#include <math.h>

#define NN 8192
#define NB 32
#define NG 256
#define NE 65536
#define DK 512
#define HH 32
#define VB 2048
#define VF 512
#define EPS 1e-5f

// ---------------- device scratch ----------------
__device__ float g_sB[NN], g_sF[NN];
__device__ __half2 g_vnB[NN * VB / 2];   // normalized visual_body fp16 (32 MB)
__device__ __half2 g_vnF[NN * VF / 2];   // normalized visual_face fp16 (8 MB)
__device__ float g_P0[DK], g_P1[DK];
__device__ float g_M1[DK], g_M2[DK], g_M3[DK];
__device__ float g_cst[12];

// ---------------- helpers ----------------
__device__ __forceinline__ float blockReduceSum(float v, float* red) {
    int t = threadIdx.x;
    red[t] = v;
    __syncthreads();
    for (int s = blockDim.x >> 1; s > 0; s >>= 1) {
        if (t < s) red[t] += red[t + s];
        __syncthreads();
    }
    float r = red[0];
    __syncthreads();
    return r;
}

__device__ __forceinline__ float warpSum(float v) {
    #pragma unroll
    for (int o = 16; o; o >>= 1) v += __shfl_xor_sync(0xFFFFFFFFu, v, o);
    return v;
}

// ---------------- K0: precompute constants ----------------
__global__ void precompute_kernel(
    const float* __restrict__ Wq, const float* __restrict__ Wk, const float* __restrict__ Wv,
    const float* __restrict__ mlp_W, const float* __restrict__ mlp_b,
    const float* __restrict__ np_W, const float* __restrict__ np_b,
    const float* __restrict__ body_W, const float* __restrict__ body_b,
    const float* __restrict__ face_W, const float* __restrict__ face_b,
    const float* __restrict__ pb_W, const float* __restrict__ pb_b,
    const float* __restrict__ pf_W, const float* __restrict__ pf_b)
{
    __shared__ float red[512];
    __shared__ float sh_u2[HH], sh_u3[HH];
    __shared__ float sh_res[12];
    int t = threadIdx.x;   // 512 threads

    if (t < HH) {
        float a2 = 0.f, a3 = 0.f;
        #pragma unroll
        for (int j = 0; j < HH; ++j) {
            a2 += body_W[t * HH + j] * pb_W[j];
            a3 += face_W[t * HH + j] * pf_W[j];
        }
        sh_u2[t] = a2;
        sh_u3[t] = a3;
    }
    __syncthreads();

    float wq0 = Wq[t], wq1 = Wq[DK + t];
    float wk0 = Wk[t], wk1 = Wk[DK + t];
    float wv0 = Wv[t], wv1 = Wv[DK + t];

    float g00 = blockReduceSum(wq0 * wk0, red);
    float g01 = blockReduceSum(wq0 * wk1, red);
    float g10 = blockReduceSum(wq1 * wk0, red);
    float g11 = blockReduceSum(wq1 * wk1, red);
    float sum0 = blockReduceSum(wv0, red);
    float sum1 = blockReduceSum(wv1, red);
    float sq00 = blockReduceSum(wv0 * wv0, red);
    float sq01 = blockReduceSum(wv0 * wv1, red);
    float sq11 = blockReduceSum(wv1 * wv1, red);
    float bu1 = blockReduceSum(t < HH ? mlp_b[t] * np_W[t] : 0.f, red);
    float bu2 = blockReduceSum(t < HH ? mlp_b[t] * sh_u2[t] : 0.f, red);
    float bu3 = blockReduceSum(t < HH ? mlp_b[t] * sh_u3[t] : 0.f, red);
    float bvB = blockReduceSum(t < HH ? body_b[t] * pb_W[t] : 0.f, red);
    float bvF = blockReduceSum(t < HH ? face_b[t] * pf_W[t] : 0.f, red);

    if (t == 0) {
        float m0 = sum0 / (float)DK, m1 = sum1 / (float)DK;
        sh_res[0] = g00; sh_res[1] = g01; sh_res[2] = g10; sh_res[3] = g11;
        sh_res[4] = sq00 / (float)DK - m0 * m0;
        sh_res[5] = sq01 / (float)DK - m0 * m1;
        sh_res[6] = sq11 / (float)DK - m1 * m1;
        sh_res[7] = bu1 + np_b[0] + pb_b[0] + pf_b[0];
        sh_res[8] = bu2 + bvB;
        sh_res[9] = bu3 + bvF;
        sh_res[10] = m0;
        sh_res[11] = m1;
    }
    __syncthreads();

    if (t < 12) g_cst[t] = sh_res[t];

    float m0 = sh_res[10], m1 = sh_res[11];
    g_P0[t] = wv0 - m0;
    g_P1[t] = wv1 - m1;

    float a1 = 0.f, a2 = 0.f, a3 = 0.f;
    #pragma unroll
    for (int l = 0; l < HH; ++l) {
        float w = mlp_W[t * HH + l];
        a1 += w * np_W[l];
        a2 += w * sh_u2[l];
        a3 += w * sh_u3[l];
    }
    g_M1[t] = a1;
    g_M2[t] = a2;
    g_M3[t] = a3;
}

// ---------------- merged kernel: norm (body+face) blocks + attn_node blocks ----------------
// grid layout: [0,1024) body norm (warp/row), [1024,2048) face norm (warp/row),
//              [2048,3072) attn+node (same as before). 256 threads.
#define MB_BODY 1024
#define MB_FACE 1024
#define MB_ATTN (NB * 32)

__global__ void norm_attn_kernel(const float* __restrict__ visB, const float* __restrict__ visF,
                                 const float* __restrict__ x,
                                 const float* __restrict__ ln_g, const float* __restrict__ ln_b,
                                 const float* __restrict__ prelu_a, float* __restrict__ out) {
    __shared__ float sa[NG], sb[NG];
    int b = blockIdx.x;
    int t = threadIdx.x;
    int lane = t & 31;

    if (b < MB_BODY) {
        // ---- body norm: warp per row, full-row register prefetch (16 float4/lane) ----
        int row = (b * 256 + t) >> 5;
        const float4* v = reinterpret_cast<const float4*>(visB) + (size_t)row * (VB / 4) + lane;
        float4 r[16];
        #pragma unroll
        for (int i = 0; i < 16; ++i) r[i] = v[i * 32];
        float acc = 0.f;
        #pragma unroll
        for (int i = 0; i < 16; ++i)
            acc += r[i].x * r[i].x + r[i].y * r[i].y + r[i].z * r[i].z + r[i].w * r[i].w;
        acc = warpSum(acc);
        float rs = rsqrtf(acc + 1e-8f);
        uint2* o = reinterpret_cast<uint2*>(g_vnB) + (size_t)row * (VB / 4) + lane;
        #pragma unroll
        for (int i = 0; i < 16; ++i) {
            __half2 h0 = __floats2half2_rn(r[i].x * rs, r[i].y * rs);
            __half2 h1 = __floats2half2_rn(r[i].z * rs, r[i].w * rs);
            uint2 u;
            u.x = *reinterpret_cast<unsigned*>(&h0);
            u.y = *reinterpret_cast<unsigned*>(&h1);
            o[i * 32] = u;
        }
    } else if (b < MB_BODY + MB_FACE) {
        // ---- face norm: warp per row, 4 float4/lane ----
        int row = ((b - MB_BODY) * 256 + t) >> 5;
        const float4* v = reinterpret_cast<const float4*>(visF) + (size_t)row * (VF / 4) + lane;
        float4 r[4];
        #pragma unroll
        for (int i = 0; i < 4; ++i) r[i] = v[i * 32];
        float acc = 0.f;
        #pragma unroll
        for (int i = 0; i < 4; ++i)
            acc += r[i].x * r[i].x + r[i].y * r[i].y + r[i].z * r[i].z + r[i].w * r[i].w;
        acc = warpSum(acc);
        float rs = rsqrtf(acc + 1e-8f);
        uint2* o = reinterpret_cast<uint2*>(g_vnF) + (size_t)row * (VF / 4) + lane;
        #pragma unroll
        for (int i = 0; i < 4; ++i) {
            __half2 h0 = __floats2half2_rn(r[i].x * rs, r[i].y * rs);
            __half2 h1 = __floats2half2_rn(r[i].z * rs, r[i].w * rs);
            uint2 u;
            u.x = *reinterpret_cast<unsigned*>(&h0);
            u.y = *reinterpret_cast<unsigned*>(&h1);
            o[i * 32] = u;
        }
    } else {
        // ---- attention + node stage ----
        int idx = b - (MB_BODY + MB_FACE);
        int g = idx >> 5;
        int bi = idx & 31;
        int node = g * NG + t;
        sa[t] = x[2 * node];
        sb[t] = x[2 * node + 1];
        __syncthreads();

        float g00 = g_cst[0], g01 = g_cst[1], g10 = g_cst[2], g11 = g_cst[3];
        const float inv = 0.04419417382415922f;
        int warp = t >> 5;
        int i = bi * 8 + warp;

        float ai = sa[i], bi2 = sb[i];
        float alpha = (ai * g00 + bi2 * g10) * inv;
        float beta  = (ai * g01 + bi2 * g11) * inv;
        float m = -1e30f;
        #pragma unroll
        for (int j = lane; j < NG; j += 32)
            m = fmaxf(m, alpha * sa[j] + beta * sb[j]);
        #pragma unroll
        for (int o = 16; o; o >>= 1) m = fmaxf(m, __shfl_xor_sync(0xFFFFFFFFu, m, o));
        float s = 0.f, sA = 0.f, sBv = 0.f;
        #pragma unroll
        for (int j = lane; j < NG; j += 32) {
            float e = __expf(alpha * sa[j] + beta * sb[j] - m);
            s += e; sA += e * sa[j]; sBv += e * sb[j];
        }
        s = warpSum(s); sA = warpSum(sA); sBv = warpSum(sBv);
        float c = sA / s, d = sBv / s;

        float s00 = g_cst[4], s01 = g_cst[5], s11 = g_cst[6];
        float var = c * c * s00 + 2.f * c * d * s01 + d * d * s11;
        float rstd = rsqrtf(var + EPS);
        float a = prelu_a[0];
        float acc1 = 0.f, acc2 = 0.f, acc3 = 0.f;
        #pragma unroll
        for (int k = lane; k < DK; k += 32) {
            float z = (c * g_P0[k] + d * g_P1[k]) * rstd;
            float tv = z * ln_g[k] + ln_b[k];
            tv = tv >= 0.f ? tv : a * tv;
            acc1 += tv * g_M1[k];
            acc2 += tv * g_M2[k];
            acc3 += tv * g_M3[k];
        }
        acc1 = warpSum(acc1); acc2 = warpSum(acc2); acc3 = warpSum(acc3);
        if (lane == 0) {
            int n = g * NG + i;
            out[n]  = acc1 + g_cst[7];
            g_sB[n] = acc2 + g_cst[8];
            g_sF[n] = acc3 + g_cst[9];
        }
    }
}

// ---------------- K_edge: merged body+face, deep prefetch (unchanged from R5) ----------------
#define EDGE_TPB 128
#define BODY_WARPS NE                 // 65536 warps
#define FACE_WARPS (NE / 2)           // 32768 warps
#define BODY_BLOCKS (BODY_WARPS * 32 / EDGE_TPB)   // 16384
#define FACE_BLOCKS (FACE_WARPS * 32 / EDGE_TPB)   // 8192

__global__ void edge_kernel(const int* __restrict__ eiB, const int* __restrict__ eiF,
                            float* __restrict__ out) {
    int gw = (blockIdx.x * EDGE_TPB + threadIdx.x) >> 5;
    int lane = threadIdx.x & 31;

    if (gw < BODY_WARPS) {
        int e = gw;
        int src = eiB[e], dst = eiB[NE + e];
        const int4* a = reinterpret_cast<const int4*>(g_vnB) + (size_t)src * (VB / 8) + lane;
        const int4* b = reinterpret_cast<const int4*>(g_vnB) + (size_t)dst * (VB / 8) + lane;
        int4 ra[8], rb[8];
        #pragma unroll
        for (int i = 0; i < 8; ++i) ra[i] = a[i * 32];
        #pragma unroll
        for (int i = 0; i < 8; ++i) rb[i] = b[i * 32];
        float acc0 = 0.f, acc1 = 0.f;
        #pragma unroll
        for (int i = 0; i < 8; ++i) {
            const __half2* ha = reinterpret_cast<const __half2*>(&ra[i]);
            const __half2* hb = reinterpret_cast<const __half2*>(&rb[i]);
            #pragma unroll
            for (int u = 0; u < 4; ++u) {
                float2 fa = __half22float2(ha[u]);
                float2 fb = __half22float2(hb[u]);
                acc0 += fa.x * fb.x;
                acc1 += fa.y * fb.y;
            }
        }
        float acc = warpSum(acc0 + acc1);
        if (lane == 0) atomicAdd(&out[dst], acc * g_sB[src]);
    } else {
        int e = (gw - BODY_WARPS) * 2 + (lane >> 4);
        int hl = lane & 15;
        int src = eiF[e], dst = eiF[NE + e];
        const int4* a = reinterpret_cast<const int4*>(g_vnF) + (size_t)src * (VF / 8) + hl;
        const int4* b = reinterpret_cast<const int4*>(g_vnF) + (size_t)dst * (VF / 8) + hl;
        int4 ra[4], rb[4];
        #pragma unroll
        for (int i = 0; i < 4; ++i) ra[i] = a[i * 16];
        #pragma unroll
        for (int i = 0; i < 4; ++i) rb[i] = b[i * 16];
        float acc0 = 0.f, acc1 = 0.f;
        #pragma unroll
        for (int i = 0; i < 4; ++i) {
            const __half2* ha = reinterpret_cast<const __half2*>(&ra[i]);
            const __half2* hb = reinterpret_cast<const __half2*>(&rb[i]);
            #pragma unroll
            for (int u = 0; u < 4; ++u) {
                float2 fa = __half22float2(ha[u]);
                float2 fb = __half22float2(hb[u]);
                acc0 += fa.x * fb.x;
                acc1 += fa.y * fb.y;
            }
        }
        float acc = acc0 + acc1;
        #pragma unroll
        for (int o = 8; o; o >>= 1) acc += __shfl_xor_sync(0xFFFFFFFFu, acc, o);
        if (hl == 0) atomicAdd(&out[dst], acc * g_sF[src]);
    }
}

// ---------------- launch ----------------
extern "C" void kernel_launch(void* const* d_in, const int* in_sizes, int n_in,
                              void* d_out, int out_size) {
    const float* x           = (const float*)d_in[0];
    const float* visual_body = (const float*)d_in[1];
    const float* visual_face = (const float*)d_in[2];
    const float* Wq          = (const float*)d_in[3];
    const float* Wk          = (const float*)d_in[4];
    const float* Wv          = (const float*)d_in[5];
    const float* ln_g        = (const float*)d_in[6];
    const float* ln_b        = (const float*)d_in[7];
    const float* prelu_a     = (const float*)d_in[8];
    const float* mlp_W       = (const float*)d_in[9];
    const float* mlp_b       = (const float*)d_in[10];
    const float* np_W        = (const float*)d_in[11];
    const float* np_b        = (const float*)d_in[12];
    const float* body_W      = (const float*)d_in[13];
    const float* body_b      = (const float*)d_in[14];
    const float* face_W      = (const float*)d_in[15];
    const float* face_b      = (const float*)d_in[16];
    const float* pb_W        = (const float*)d_in[17];
    const float* pb_b        = (const float*)d_in[18];
    const float* pf_W        = (const float*)d_in[19];
    const float* pf_b        = (const float*)d_in[20];
    const int*   ei_body     = (const int*)d_in[21];
    const int*   ei_face     = (const int*)d_in[22];
    float* out = (float*)d_out;

    precompute_kernel<<<1, 512>>>(Wq, Wk, Wv, mlp_W, mlp_b, np_W, np_b,
                                  body_W, body_b, face_W, face_b,
                                  pb_W, pb_b, pf_W, pf_b);

    // merged: visual normalization (DRAM-bound) co-scheduled with attention+node (compute-bound)
    norm_attn_kernel<<<MB_BODY + MB_FACE + MB_ATTN, 256>>>(
        visual_body, visual_face, x, ln_g, ln_b, prelu_a, out);

    // merged edge reduction, deep prefetch
    edge_kernel<<<BODY_BLOCKS + FACE_BLOCKS, EDGE_TPB>>>(ei_body, ei_face, out);
}

// round 7
// speedup vs baseline: 1.8686x; 1.1138x over previous
#include <cuda_runtime.h>
#include <cuda_fp16.h>
#include <math.h>

#define NN 8192
#define NB 32
#define NG 256
#define NE 65536
#define DK 512
#define HH 32
#define VB 2048
#define VF 512
#define EPS 1e-5f

// ---------------- device scratch ----------------
__device__ float g_sB[NN], g_sF[NN];
__device__ __half2 g_vnB[NN * VB / 2];   // normalized visual_body fp16 (32 MB)
__device__ __half2 g_vnF[NN * VF / 2];   // normalized visual_face fp16 (8 MB)
__device__ float g_P0[DK], g_P1[DK];
__device__ float g_M1[DK], g_M2[DK], g_M3[DK];
__device__ float g_cst[12];

__device__ __forceinline__ float warpSum(float v) {
    #pragma unroll
    for (int o = 16; o; o >>= 1) v += __shfl_xor_sync(0xFFFFFFFFu, v, o);
    return v;
}

// ---------------- K0: precompute constants (shuffle-parallel, 2 barriers) ----------------
__global__ void precompute_kernel(
    const float* __restrict__ Wq, const float* __restrict__ Wk, const float* __restrict__ Wv,
    const float* __restrict__ mlp_W, const float* __restrict__ mlp_b,
    const float* __restrict__ np_W, const float* __restrict__ np_b,
    const float* __restrict__ body_W, const float* __restrict__ body_b,
    const float* __restrict__ face_W, const float* __restrict__ face_b,
    const float* __restrict__ pb_W, const float* __restrict__ pb_b,
    const float* __restrict__ pf_W, const float* __restrict__ pf_b)
{
    __shared__ float sh_u2[HH], sh_u3[HH], sh_np[HH];
    __shared__ float sh_part[16][9];
    __shared__ float sh_res[12];
    int t = threadIdx.x;          // 512 threads
    int warp = t >> 5, lane = t & 31;

    // small 32x32 matvecs + cache np_W in smem (threads 0..31)
    if (t < HH) {
        float a2 = 0.f, a3 = 0.f;
        #pragma unroll
        for (int j = 0; j < HH; ++j) {
            a2 += body_W[t * HH + j] * pb_W[j];
            a3 += face_W[t * HH + j] * pf_W[j];
        }
        sh_u2[t] = a2;
        sh_u3[t] = a3;
        sh_np[t] = np_W[t];
    }

    // nine 512-length reductions, all in one shuffle pass (no barriers)
    float wq0 = Wq[t], wq1 = Wq[DK + t];
    float wk0 = Wk[t], wk1 = Wk[DK + t];
    float wv0 = Wv[t], wv1 = Wv[DK + t];

    float v0 = warpSum(wq0 * wk0);
    float v1 = warpSum(wq0 * wk1);
    float v2 = warpSum(wq1 * wk0);
    float v3 = warpSum(wq1 * wk1);
    float v4 = warpSum(wv0);
    float v5 = warpSum(wv1);
    float v6 = warpSum(wv0 * wv0);
    float v7 = warpSum(wv0 * wv1);
    float v8 = warpSum(wv1 * wv1);
    if (lane == 0) {
        sh_part[warp][0] = v0; sh_part[warp][1] = v1; sh_part[warp][2] = v2;
        sh_part[warp][3] = v3; sh_part[warp][4] = v4; sh_part[warp][5] = v5;
        sh_part[warp][6] = v6; sh_part[warp][7] = v7; sh_part[warp][8] = v8;
    }
    __syncthreads();

    if (warp == 0) {
        // five 32-length reductions (need sh_u2/u3 ready)
        float mb = mlp_b[lane];
        float b1 = warpSum(mb * sh_np[lane]);
        float b2 = warpSum(mb * sh_u2[lane]);
        float b3 = warpSum(mb * sh_u3[lane]);
        float vBv = warpSum(body_b[lane] * pb_W[lane]);
        float vFv = warpSum(face_b[lane] * pf_W[lane]);
        if (lane == 0) {
            float r[9];
            #pragma unroll
            for (int i = 0; i < 9; ++i) {
                float s = 0.f;
                #pragma unroll
                for (int w = 0; w < 16; ++w) s += sh_part[w][i];
                r[i] = s;
            }
            float m0 = r[4] / (float)DK, m1 = r[5] / (float)DK;
            sh_res[0] = r[0]; sh_res[1] = r[1]; sh_res[2] = r[2]; sh_res[3] = r[3];
            sh_res[4] = r[6] / (float)DK - m0 * m0;
            sh_res[5] = r[7] / (float)DK - m0 * m1;
            sh_res[6] = r[8] / (float)DK - m1 * m1;
            sh_res[7] = b1 + np_b[0] + pb_b[0] + pf_b[0];
            sh_res[8] = b2 + vBv;
            sh_res[9] = b3 + vFv;
            sh_res[10] = m0;
            sh_res[11] = m1;
        }
    }
    __syncthreads();

    if (t < 12) g_cst[t] = sh_res[t];

    g_P0[t] = wv0 - sh_res[10];
    g_P1[t] = wv1 - sh_res[11];

    float a1 = 0.f, a2 = 0.f, a3 = 0.f;
    #pragma unroll
    for (int l = 0; l < HH; ++l) {
        float w = mlp_W[t * HH + l];
        a1 += w * sh_np[l];
        a2 += w * sh_u2[l];
        a3 += w * sh_u3[l];
    }
    g_M1[t] = a1;
    g_M2[t] = a2;
    g_M3[t] = a3;
}

// ---------------- merged kernel: norm (body+face) blocks + attn_node blocks ----------------
#define MB_BODY 1024
#define MB_FACE 1024
#define MB_ATTN (NB * 32)

__global__ void norm_attn_kernel(const float* __restrict__ visB, const float* __restrict__ visF,
                                 const float* __restrict__ x,
                                 const float* __restrict__ ln_g, const float* __restrict__ ln_b,
                                 const float* __restrict__ prelu_a, float* __restrict__ out) {
    __shared__ float sa[NG], sb[NG];
    int b = blockIdx.x;
    int t = threadIdx.x;
    int lane = t & 31;

    if (b < MB_BODY) {
        int row = (b * 256 + t) >> 5;
        const float4* v = reinterpret_cast<const float4*>(visB) + (size_t)row * (VB / 4) + lane;
        float4 r[16];
        #pragma unroll
        for (int i = 0; i < 16; ++i) r[i] = v[i * 32];
        float acc = 0.f;
        #pragma unroll
        for (int i = 0; i < 16; ++i)
            acc += r[i].x * r[i].x + r[i].y * r[i].y + r[i].z * r[i].z + r[i].w * r[i].w;
        acc = warpSum(acc);
        float rs = rsqrtf(acc + 1e-8f);
        uint2* o = reinterpret_cast<uint2*>(g_vnB) + (size_t)row * (VB / 4) + lane;
        #pragma unroll
        for (int i = 0; i < 16; ++i) {
            __half2 h0 = __floats2half2_rn(r[i].x * rs, r[i].y * rs);
            __half2 h1 = __floats2half2_rn(r[i].z * rs, r[i].w * rs);
            uint2 u;
            u.x = *reinterpret_cast<unsigned*>(&h0);
            u.y = *reinterpret_cast<unsigned*>(&h1);
            o[i * 32] = u;
        }
    } else if (b < MB_BODY + MB_FACE) {
        int row = ((b - MB_BODY) * 256 + t) >> 5;
        const float4* v = reinterpret_cast<const float4*>(visF) + (size_t)row * (VF / 4) + lane;
        float4 r[4];
        #pragma unroll
        for (int i = 0; i < 4; ++i) r[i] = v[i * 32];
        float acc = 0.f;
        #pragma unroll
        for (int i = 0; i < 4; ++i)
            acc += r[i].x * r[i].x + r[i].y * r[i].y + r[i].z * r[i].z + r[i].w * r[i].w;
        acc = warpSum(acc);
        float rs = rsqrtf(acc + 1e-8f);
        uint2* o = reinterpret_cast<uint2*>(g_vnF) + (size_t)row * (VF / 4) + lane;
        #pragma unroll
        for (int i = 0; i < 4; ++i) {
            __half2 h0 = __floats2half2_rn(r[i].x * rs, r[i].y * rs);
            __half2 h1 = __floats2half2_rn(r[i].z * rs, r[i].w * rs);
            uint2 u;
            u.x = *reinterpret_cast<unsigned*>(&h0);
            u.y = *reinterpret_cast<unsigned*>(&h1);
            o[i * 32] = u;
        }
    } else {
        int idx = b - (MB_BODY + MB_FACE);
        int g = idx >> 5;
        int bi = idx & 31;
        int node = g * NG + t;
        sa[t] = x[2 * node];
        sb[t] = x[2 * node + 1];
        __syncthreads();

        float g00 = g_cst[0], g01 = g_cst[1], g10 = g_cst[2], g11 = g_cst[3];
        const float inv = 0.04419417382415922f;
        int warp = t >> 5;
        int i = bi * 8 + warp;

        float ai = sa[i], bi2 = sb[i];
        float alpha = (ai * g00 + bi2 * g10) * inv;
        float beta  = (ai * g01 + bi2 * g11) * inv;
        float m = -1e30f;
        #pragma unroll
        for (int j = lane; j < NG; j += 32)
            m = fmaxf(m, alpha * sa[j] + beta * sb[j]);
        #pragma unroll
        for (int o = 16; o; o >>= 1) m = fmaxf(m, __shfl_xor_sync(0xFFFFFFFFu, m, o));
        float s = 0.f, sA = 0.f, sBv = 0.f;
        #pragma unroll
        for (int j = lane; j < NG; j += 32) {
            float e = __expf(alpha * sa[j] + beta * sb[j] - m);
            s += e; sA += e * sa[j]; sBv += e * sb[j];
        }
        s = warpSum(s); sA = warpSum(sA); sBv = warpSum(sBv);
        float c = sA / s, d = sBv / s;

        float s00 = g_cst[4], s01 = g_cst[5], s11 = g_cst[6];
        float var = c * c * s00 + 2.f * c * d * s01 + d * d * s11;
        float rstd = rsqrtf(var + EPS);
        float a = prelu_a[0];
        float acc1 = 0.f, acc2 = 0.f, acc3 = 0.f;
        #pragma unroll
        for (int k = lane; k < DK; k += 32) {
            float z = (c * g_P0[k] + d * g_P1[k]) * rstd;
            float tv = z * ln_g[k] + ln_b[k];
            tv = tv >= 0.f ? tv : a * tv;
            acc1 += tv * g_M1[k];
            acc2 += tv * g_M2[k];
            acc3 += tv * g_M3[k];
        }
        acc1 = warpSum(acc1); acc2 = warpSum(acc2); acc3 = warpSum(acc3);
        if (lane == 0) {
            int n = g * NG + i;
            out[n]  = acc1 + g_cst[7];
            g_sB[n] = acc2 + g_cst[8];
            g_sF[n] = acc3 + g_cst[9];
        }
    }
}

// ---------------- K_edge: merged body+face, deep prefetch ----------------
#define EDGE_TPB 128
#define BODY_WARPS NE                 // 65536 warps
#define FACE_WARPS (NE / 2)           // 32768 warps
#define BODY_BLOCKS (BODY_WARPS * 32 / EDGE_TPB)   // 16384
#define FACE_BLOCKS (FACE_WARPS * 32 / EDGE_TPB)   // 8192

__global__ void edge_kernel(const int* __restrict__ eiB, const int* __restrict__ eiF,
                            float* __restrict__ out) {
    int gw = (blockIdx.x * EDGE_TPB + threadIdx.x) >> 5;
    int lane = threadIdx.x & 31;

    if (gw < BODY_WARPS) {
        int e = gw;
        int src = eiB[e], dst = eiB[NE + e];
        const int4* a = reinterpret_cast<const int4*>(g_vnB) + (size_t)src * (VB / 8) + lane;
        const int4* b = reinterpret_cast<const int4*>(g_vnB) + (size_t)dst * (VB / 8) + lane;
        int4 ra[8], rb[8];
        #pragma unroll
        for (int i = 0; i < 8; ++i) ra[i] = a[i * 32];
        #pragma unroll
        for (int i = 0; i < 8; ++i) rb[i] = b[i * 32];
        float acc0 = 0.f, acc1 = 0.f;
        #pragma unroll
        for (int i = 0; i < 8; ++i) {
            const __half2* ha = reinterpret_cast<const __half2*>(&ra[i]);
            const __half2* hb = reinterpret_cast<const __half2*>(&rb[i]);
            #pragma unroll
            for (int u = 0; u < 4; ++u) {
                float2 fa = __half22float2(ha[u]);
                float2 fb = __half22float2(hb[u]);
                acc0 += fa.x * fb.x;
                acc1 += fa.y * fb.y;
            }
        }
        float acc = warpSum(acc0 + acc1);
        if (lane == 0) atomicAdd(&out[dst], acc * g_sB[src]);
    } else {
        int e = (gw - BODY_WARPS) * 2 + (lane >> 4);
        int hl = lane & 15;
        int src = eiF[e], dst = eiF[NE + e];
        const int4* a = reinterpret_cast<const int4*>(g_vnF) + (size_t)src * (VF / 8) + hl;
        const int4* b = reinterpret_cast<const int4*>(g_vnF) + (size_t)dst * (VF / 8) + hl;
        int4 ra[4], rb[4];
        #pragma unroll
        for (int i = 0; i < 4; ++i) ra[i] = a[i * 16];
        #pragma unroll
        for (int i = 0; i < 4; ++i) rb[i] = b[i * 16];
        float acc0 = 0.f, acc1 = 0.f;
        #pragma unroll
        for (int i = 0; i < 4; ++i) {
            const __half2* ha = reinterpret_cast<const __half2*>(&ra[i]);
            const __half2* hb = reinterpret_cast<const __half2*>(&rb[i]);
            #pragma unroll
            for (int u = 0; u < 4; ++u) {
                float2 fa = __half22float2(ha[u]);
                float2 fb = __half22float2(hb[u]);
                acc0 += fa.x * fb.x;
                acc1 += fa.y * fb.y;
            }
        }
        float acc = acc0 + acc1;
        #pragma unroll
        for (int o = 8; o; o >>= 1) acc += __shfl_xor_sync(0xFFFFFFFFu, acc, o);
        if (hl == 0) atomicAdd(&out[dst], acc * g_sF[src]);
    }
}

// ---------------- launch ----------------
extern "C" void kernel_launch(void* const* d_in, const int* in_sizes, int n_in,
                              void* d_out, int out_size) {
    const float* x           = (const float*)d_in[0];
    const float* visual_body = (const float*)d_in[1];
    const float* visual_face = (const float*)d_in[2];
    const float* Wq          = (const float*)d_in[3];
    const float* Wk          = (const float*)d_in[4];
    const float* Wv          = (const float*)d_in[5];
    const float* ln_g        = (const float*)d_in[6];
    const float* ln_b        = (const float*)d_in[7];
    const float* prelu_a     = (const float*)d_in[8];
    const float* mlp_W       = (const float*)d_in[9];
    const float* mlp_b       = (const float*)d_in[10];
    const float* np_W        = (const float*)d_in[11];
    const float* np_b        = (const float*)d_in[12];
    const float* body_W      = (const float*)d_in[13];
    const float* body_b      = (const float*)d_in[14];
    const float* face_W      = (const float*)d_in[15];
    const float* face_b      = (const float*)d_in[16];
    const float* pb_W        = (const float*)d_in[17];
    const float* pb_b        = (const float*)d_in[18];
    const float* pf_W        = (const float*)d_in[19];
    const float* pf_b        = (const float*)d_in[20];
    const int*   ei_body     = (const int*)d_in[21];
    const int*   ei_face     = (const int*)d_in[22];
    float* out = (float*)d_out;

    precompute_kernel<<<1, 512>>>(Wq, Wk, Wv, mlp_W, mlp_b, np_W, np_b,
                                  body_W, body_b, face_W, face_b,
                                  pb_W, pb_b, pf_W, pf_b);

    norm_attn_kernel<<<MB_BODY + MB_FACE + MB_ATTN, 256>>>(
        visual_body, visual_face, x, ln_g, ln_b, prelu_a, out);

    edge_kernel<<<BODY_BLOCKS + FACE_BLOCKS, EDGE_TPB>>>(ei_body, ei_face, out);
}

// round 8
// speedup vs baseline: 2.0691x; 1.1073x over previous
#include <cuda_runtime.h>
#include <cuda_fp16.h>
#include <math.h>

#define NN 8192
#define NB 32
#define NG 256
#define NE 65536
#define DK 512
#define HH 32
#define VB 2048
#define VF 512
#define EPS 1e-5f

// ---------------- device scratch ----------------
__device__ float g_sB[NN], g_sF[NN];
__device__ __half2 g_vnB[NN * VB / 2];   // normalized visual_body fp16 (32 MB)
__device__ __half2 g_vnF[NN * VF / 2];   // normalized visual_face fp16 (8 MB)
__device__ float g_P0[DK], g_P1[DK];
__device__ float g_M1[DK], g_M2[DK], g_M3[DK];
__device__ float g_cst[12];
__device__ float g_pad_[32];             // keep flag off the constants' cache lines
__device__ volatile int g_flag = 0;      // constants-ready flag (reset by edge_kernel)

__device__ __forceinline__ float warpSum(float v) {
    #pragma unroll
    for (int o = 16; o; o >>= 1) v += __shfl_xor_sync(0xFFFFFFFFu, v, o);
    return v;
}

// ---------------- merged kernel ----------------
// grid layout (256 threads each):
//   block 0                       : precompute constants, then raise g_flag
//   blocks [1, 1+1024)            : body norm (warp per row)
//   blocks [1+1024, 1+2048)       : face norm (warp per row)
//   blocks [1+2048, 1+3072)       : attention + node stage (spin on g_flag)
#define MB_BODY 1024
#define MB_FACE 1024
#define MB_ATTN (NB * 32)
#define GRID_TOTAL (1 + MB_BODY + MB_FACE + MB_ATTN)

__global__ void norm_attn_kernel(const float* __restrict__ visB, const float* __restrict__ visF,
                                 const float* __restrict__ x,
                                 const float* __restrict__ ln_g, const float* __restrict__ ln_b,
                                 const float* __restrict__ prelu_a,
                                 const float* __restrict__ Wq, const float* __restrict__ Wk,
                                 const float* __restrict__ Wv,
                                 const float* __restrict__ mlp_W, const float* __restrict__ mlp_b,
                                 const float* __restrict__ np_W, const float* __restrict__ np_b,
                                 const float* __restrict__ body_W, const float* __restrict__ body_b,
                                 const float* __restrict__ face_W, const float* __restrict__ face_b,
                                 const float* __restrict__ pb_W, const float* __restrict__ pb_b,
                                 const float* __restrict__ pf_W, const float* __restrict__ pf_b,
                                 float* __restrict__ out) {
    __shared__ float sa[NG], sb[NG];
    int b = blockIdx.x;
    int t = threadIdx.x;
    int lane = t & 31;
    int warp = t >> 5;

    if (b == 0) {
        // ---------------- precompute constants (256 threads, 2 dims each) ----------------
        __shared__ float sh_u2[HH], sh_u3[HH], sh_np[HH];
        __shared__ float sh_part[8][9];
        __shared__ float sh_res[12];
        int k1 = t, k2 = t + 256;

        if (t < HH) {
            float a2 = 0.f, a3 = 0.f;
            #pragma unroll
            for (int j = 0; j < HH; ++j) {
                a2 += body_W[t * HH + j] * pb_W[j];
                a3 += face_W[t * HH + j] * pf_W[j];
            }
            sh_u2[t] = a2;
            sh_u3[t] = a3;
            sh_np[t] = np_W[t];
        }

        float wq0a = Wq[k1], wq0b = Wq[k2], wq1a = Wq[DK + k1], wq1b = Wq[DK + k2];
        float wk0a = Wk[k1], wk0b = Wk[k2], wk1a = Wk[DK + k1], wk1b = Wk[DK + k2];
        float wv0a = Wv[k1], wv0b = Wv[k2], wv1a = Wv[DK + k1], wv1b = Wv[DK + k2];

        float v0 = warpSum(wq0a * wk0a + wq0b * wk0b);
        float v1 = warpSum(wq0a * wk1a + wq0b * wk1b);
        float v2 = warpSum(wq1a * wk0a + wq1b * wk0b);
        float v3 = warpSum(wq1a * wk1a + wq1b * wk1b);
        float v4 = warpSum(wv0a + wv0b);
        float v5 = warpSum(wv1a + wv1b);
        float v6 = warpSum(wv0a * wv0a + wv0b * wv0b);
        float v7 = warpSum(wv0a * wv1a + wv0b * wv1b);
        float v8 = warpSum(wv1a * wv1a + wv1b * wv1b);
        if (lane == 0) {
            sh_part[warp][0] = v0; sh_part[warp][1] = v1; sh_part[warp][2] = v2;
            sh_part[warp][3] = v3; sh_part[warp][4] = v4; sh_part[warp][5] = v5;
            sh_part[warp][6] = v6; sh_part[warp][7] = v7; sh_part[warp][8] = v8;
        }
        __syncthreads();

        if (warp == 0) {
            float mb = mlp_b[lane];
            float b1 = warpSum(mb * sh_np[lane]);
            float b2 = warpSum(mb * sh_u2[lane]);
            float b3 = warpSum(mb * sh_u3[lane]);
            float vBv = warpSum(body_b[lane] * pb_W[lane]);
            float vFv = warpSum(face_b[lane] * pf_W[lane]);
            if (lane == 0) {
                float r[9];
                #pragma unroll
                for (int i = 0; i < 9; ++i) {
                    float s = 0.f;
                    #pragma unroll
                    for (int w = 0; w < 8; ++w) s += sh_part[w][i];
                    r[i] = s;
                }
                float m0 = r[4] / (float)DK, m1 = r[5] / (float)DK;
                sh_res[0] = r[0]; sh_res[1] = r[1]; sh_res[2] = r[2]; sh_res[3] = r[3];
                sh_res[4] = r[6] / (float)DK - m0 * m0;
                sh_res[5] = r[7] / (float)DK - m0 * m1;
                sh_res[6] = r[8] / (float)DK - m1 * m1;
                sh_res[7] = b1 + np_b[0] + pb_b[0] + pf_b[0];
                sh_res[8] = b2 + vBv;
                sh_res[9] = b3 + vFv;
                sh_res[10] = m0;
                sh_res[11] = m1;
            }
        }
        __syncthreads();

        if (t < 12) g_cst[t] = sh_res[t];
        g_P0[k1] = wv0a - sh_res[10];
        g_P0[k2] = wv0b - sh_res[10];
        g_P1[k1] = wv1a - sh_res[11];
        g_P1[k2] = wv1b - sh_res[11];

        float a1a = 0.f, a2a = 0.f, a3a = 0.f, a1b = 0.f, a2b = 0.f, a3b = 0.f;
        #pragma unroll
        for (int l = 0; l < HH; ++l) {
            float wa = mlp_W[k1 * HH + l];
            float wb = mlp_W[k2 * HH + l];
            float un = sh_np[l], u2 = sh_u2[l], u3 = sh_u3[l];
            a1a += wa * un; a2a += wa * u2; a3a += wa * u3;
            a1b += wb * un; a2b += wb * u2; a3b += wb * u3;
        }
        g_M1[k1] = a1a; g_M2[k1] = a2a; g_M3[k1] = a3a;
        g_M1[k2] = a1b; g_M2[k2] = a2b; g_M3[k2] = a3b;

        __threadfence();
        __syncthreads();
        if (t == 0) g_flag = 1;
    } else if (b < 1 + MB_BODY) {
        // ---- body norm: warp per row, full-row register prefetch ----
        int row = ((b - 1) * 256 + t) >> 5;
        const float4* v = reinterpret_cast<const float4*>(visB) + (size_t)row * (VB / 4) + lane;
        float4 r[16];
        #pragma unroll
        for (int i = 0; i < 16; ++i) r[i] = v[i * 32];
        float acc = 0.f;
        #pragma unroll
        for (int i = 0; i < 16; ++i)
            acc += r[i].x * r[i].x + r[i].y * r[i].y + r[i].z * r[i].z + r[i].w * r[i].w;
        acc = warpSum(acc);
        float rs = rsqrtf(acc + 1e-8f);
        uint2* o = reinterpret_cast<uint2*>(g_vnB) + (size_t)row * (VB / 4) + lane;
        #pragma unroll
        for (int i = 0; i < 16; ++i) {
            __half2 h0 = __floats2half2_rn(r[i].x * rs, r[i].y * rs);
            __half2 h1 = __floats2half2_rn(r[i].z * rs, r[i].w * rs);
            uint2 u;
            u.x = *reinterpret_cast<unsigned*>(&h0);
            u.y = *reinterpret_cast<unsigned*>(&h1);
            o[i * 32] = u;
        }
    } else if (b < 1 + MB_BODY + MB_FACE) {
        // ---- face norm: warp per row ----
        int row = ((b - 1 - MB_BODY) * 256 + t) >> 5;
        const float4* v = reinterpret_cast<const float4*>(visF) + (size_t)row * (VF / 4) + lane;
        float4 r[4];
        #pragma unroll
        for (int i = 0; i < 4; ++i) r[i] = v[i * 32];
        float acc = 0.f;
        #pragma unroll
        for (int i = 0; i < 4; ++i)
            acc += r[i].x * r[i].x + r[i].y * r[i].y + r[i].z * r[i].z + r[i].w * r[i].w;
        acc = warpSum(acc);
        float rs = rsqrtf(acc + 1e-8f);
        uint2* o = reinterpret_cast<uint2*>(g_vnF) + (size_t)row * (VF / 4) + lane;
        #pragma unroll
        for (int i = 0; i < 4; ++i) {
            __half2 h0 = __floats2half2_rn(r[i].x * rs, r[i].y * rs);
            __half2 h1 = __floats2half2_rn(r[i].z * rs, r[i].w * rs);
            uint2 u;
            u.x = *reinterpret_cast<unsigned*>(&h0);
            u.y = *reinterpret_cast<unsigned*>(&h1);
            o[i * 32] = u;
        }
    } else {
        // ---- attention + node stage (waits for block 0's constants) ----
        int idx = b - (1 + MB_BODY + MB_FACE);
        int g = idx >> 5;
        int bi = idx & 31;
        int node = g * NG + t;
        sa[t] = x[2 * node];
        sb[t] = x[2 * node + 1];
        if (t == 0) {
            while (g_flag == 0) {}
        }
        __syncthreads();       // orders spin before constant reads + covers sa/sb
        __threadfence();       // acquire: see block 0's global writes

        float g00 = g_cst[0], g01 = g_cst[1], g10 = g_cst[2], g11 = g_cst[3];
        const float inv = 0.04419417382415922f;
        int i = bi * 8 + warp;

        float ai = sa[i], bi2 = sb[i];
        float alpha = (ai * g00 + bi2 * g10) * inv;
        float beta  = (ai * g01 + bi2 * g11) * inv;
        float m = -1e30f;
        #pragma unroll
        for (int j = lane; j < NG; j += 32)
            m = fmaxf(m, alpha * sa[j] + beta * sb[j]);
        #pragma unroll
        for (int o = 16; o; o >>= 1) m = fmaxf(m, __shfl_xor_sync(0xFFFFFFFFu, m, o));
        float s = 0.f, sA = 0.f, sBv = 0.f;
        #pragma unroll
        for (int j = lane; j < NG; j += 32) {
            float e = __expf(alpha * sa[j] + beta * sb[j] - m);
            s += e; sA += e * sa[j]; sBv += e * sb[j];
        }
        s = warpSum(s); sA = warpSum(sA); sBv = warpSum(sBv);
        float c = sA / s, d = sBv / s;

        float s00 = g_cst[4], s01 = g_cst[5], s11 = g_cst[6];
        float var = c * c * s00 + 2.f * c * d * s01 + d * d * s11;
        float rstd = rsqrtf(var + EPS);
        float a = prelu_a[0];
        float acc1 = 0.f, acc2 = 0.f, acc3 = 0.f;
        #pragma unroll
        for (int k = lane; k < DK; k += 32) {
            float z = (c * g_P0[k] + d * g_P1[k]) * rstd;
            float tv = z * ln_g[k] + ln_b[k];
            tv = tv >= 0.f ? tv : a * tv;
            acc1 += tv * g_M1[k];
            acc2 += tv * g_M2[k];
            acc3 += tv * g_M3[k];
        }
        acc1 = warpSum(acc1); acc2 = warpSum(acc2); acc3 = warpSum(acc3);
        if (lane == 0) {
            int n = g * NG + i;
            out[n]  = acc1 + g_cst[7];
            g_sB[n] = acc2 + g_cst[8];
            g_sF[n] = acc3 + g_cst[9];
        }
    }
}

// ---------------- K_edge: merged body+face, deep prefetch ----------------
#define EDGE_TPB 128
#define BODY_WARPS NE                 // 65536 warps
#define FACE_WARPS (NE / 2)           // 32768 warps
#define BODY_BLOCKS (BODY_WARPS * 32 / EDGE_TPB)   // 16384
#define FACE_BLOCKS (FACE_WARPS * 32 / EDGE_TPB)   // 8192

__global__ void edge_kernel(const int* __restrict__ eiB, const int* __restrict__ eiF,
                            float* __restrict__ out) {
    // reset the constants flag for the next graph replay (stream-ordered after all readers)
    if (blockIdx.x == 0 && threadIdx.x == 0) g_flag = 0;

    int gw = (blockIdx.x * EDGE_TPB + threadIdx.x) >> 5;
    int lane = threadIdx.x & 31;

    if (gw < BODY_WARPS) {
        int e = gw;
        int src = eiB[e], dst = eiB[NE + e];
        const int4* a = reinterpret_cast<const int4*>(g_vnB) + (size_t)src * (VB / 8) + lane;
        const int4* b = reinterpret_cast<const int4*>(g_vnB) + (size_t)dst * (VB / 8) + lane;
        int4 ra[8], rb[8];
        #pragma unroll
        for (int i = 0; i < 8; ++i) ra[i] = a[i * 32];
        #pragma unroll
        for (int i = 0; i < 8; ++i) rb[i] = b[i * 32];
        float acc0 = 0.f, acc1 = 0.f;
        #pragma unroll
        for (int i = 0; i < 8; ++i) {
            const __half2* ha = reinterpret_cast<const __half2*>(&ra[i]);
            const __half2* hb = reinterpret_cast<const __half2*>(&rb[i]);
            #pragma unroll
            for (int u = 0; u < 4; ++u) {
                float2 fa = __half22float2(ha[u]);
                float2 fb = __half22float2(hb[u]);
                acc0 += fa.x * fb.x;
                acc1 += fa.y * fb.y;
            }
        }
        float acc = warpSum(acc0 + acc1);
        if (lane == 0) atomicAdd(&out[dst], acc * g_sB[src]);
    } else {
        int e = (gw - BODY_WARPS) * 2 + (lane >> 4);
        int hl = lane & 15;
        int src = eiF[e], dst = eiF[NE + e];
        const int4* a = reinterpret_cast<const int4*>(g_vnF) + (size_t)src * (VF / 8) + hl;
        const int4* b = reinterpret_cast<const int4*>(g_vnF) + (size_t)dst * (VF / 8) + hl;
        int4 ra[4], rb[4];
        #pragma unroll
        for (int i = 0; i < 4; ++i) ra[i] = a[i * 16];
        #pragma unroll
        for (int i = 0; i < 4; ++i) rb[i] = b[i * 16];
        float acc0 = 0.f, acc1 = 0.f;
        #pragma unroll
        for (int i = 0; i < 4; ++i) {
            const __half2* ha = reinterpret_cast<const __half2*>(&ra[i]);
            const __half2* hb = reinterpret_cast<const __half2*>(&rb[i]);
            #pragma unroll
            for (int u = 0; u < 4; ++u) {
                float2 fa = __half22float2(ha[u]);
                float2 fb = __half22float2(hb[u]);
                acc0 += fa.x * fb.x;
                acc1 += fa.y * fb.y;
            }
        }
        float acc = acc0 + acc1;
        #pragma unroll
        for (int o = 8; o; o >>= 1) acc += __shfl_xor_sync(0xFFFFFFFFu, acc, o);
        if (hl == 0) atomicAdd(&out[dst], acc * g_sF[src]);
    }
}

// ---------------- launch ----------------
extern "C" void kernel_launch(void* const* d_in, const int* in_sizes, int n_in,
                              void* d_out, int out_size) {
    const float* x           = (const float*)d_in[0];
    const float* visual_body = (const float*)d_in[1];
    const float* visual_face = (const float*)d_in[2];
    const float* Wq          = (const float*)d_in[3];
    const float* Wk          = (const float*)d_in[4];
    const float* Wv          = (const float*)d_in[5];
    const float* ln_g        = (const float*)d_in[6];
    const float* ln_b        = (const float*)d_in[7];
    const float* prelu_a     = (const float*)d_in[8];
    const float* mlp_W       = (const float*)d_in[9];
    const float* mlp_b       = (const float*)d_in[10];
    const float* np_W        = (const float*)d_in[11];
    const float* np_b        = (const float*)d_in[12];
    const float* body_W      = (const float*)d_in[13];
    const float* body_b      = (const float*)d_in[14];
    const float* face_W      = (const float*)d_in[15];
    const float* face_b      = (const float*)d_in[16];
    const float* pb_W        = (const float*)d_in[17];
    const float* pb_b        = (const float*)d_in[18];
    const float* pf_W        = (const float*)d_in[19];
    const float* pf_b        = (const float*)d_in[20];
    const int*   ei_body     = (const int*)d_in[21];
    const int*   ei_face     = (const int*)d_in[22];
    float* out = (float*)d_out;

    norm_attn_kernel<<<GRID_TOTAL, 256>>>(
        visual_body, visual_face, x, ln_g, ln_b, prelu_a,
        Wq, Wk, Wv, mlp_W, mlp_b, np_W, np_b,
        body_W, body_b, face_W, face_b, pb_W, pb_b, pf_W, pf_b, out);

    edge_kernel<<<BODY_BLOCKS + FACE_BLOCKS, EDGE_TPB>>>(ei_body, ei_face, out);
}